// round 2
// baseline (speedup 1.0000x reference)
#include <cuda_runtime.h>
#include <math.h>

// Problem dims
#define T_STEPS 512
#define BATCH   64
#define ISZ     1024
#define HSZ     1024
#define GATES   4096   // 4*HSZ

// -------- scratch (no cudaMalloc allowed; __device__ globals are the workaround) ----
__device__ float g_xp[(size_t)T_STEPS * BATCH * GATES];  // 512 MB: x @ W_ih^T + bias
__device__ float g_c[BATCH * HSZ];                       // cell state
__device__ unsigned g_count;                             // grid barrier counter

__global__ void reset_kernel() { g_count = 0u; }

// =====================================================================
// Kernel 1: g_xp[m][n] = sum_k x[m][k] * Wih[n][k] + bih[n] + bhh[n]
//           M = T*B = 32768, N = 4096, K = 1024
// CTA tile 128(M) x 64(N), 256 threads, thread tile 8x4, K-tile 16.
// =====================================================================
#define BM 128
#define BN 64
#define BK 16

__global__ __launch_bounds__(256) void xp_gemm_kernel(
    const float* __restrict__ x, const float* __restrict__ Wih,
    const float* __restrict__ bih, const float* __restrict__ bhh)
{
    __shared__ float As[BK][BM + 4];   // [k][m]
    __shared__ float Bs[BK][BN + 4];   // [k][n]
    const int m0 = blockIdx.y * BM;
    const int n0 = blockIdx.x * BN;
    const int tid = threadIdx.x;
    const int tm = tid >> 4;   // 0..15 -> 8 m's
    const int tn = tid & 15;   // 0..15 -> 4 n's

    float acc[8][4];
    #pragma unroll
    for (int i = 0; i < 8; i++)
        #pragma unroll
        for (int j = 0; j < 4; j++) acc[i][j] = 0.f;

    for (int k0 = 0; k0 < ISZ; k0 += BK) {
        // Load A tile: 128x16 floats = 512 float4, 2 per thread (transpose into [k][m])
        #pragma unroll
        for (int i = 0; i < 2; i++) {
            int idx = tid + i * 256;       // 0..511
            int m  = idx >> 2;             // 0..127
            int k4 = (idx & 3) << 2;       // 0,4,8,12
            float4 v = *(const float4*)&x[(size_t)(m0 + m) * ISZ + k0 + k4];
            As[k4 + 0][m] = v.x; As[k4 + 1][m] = v.y;
            As[k4 + 2][m] = v.z; As[k4 + 3][m] = v.w;
        }
        // Load W tile: 64x16 floats = 256 float4, 1 per thread
        {
            int n  = tid >> 2;             // 0..63
            int k4 = (tid & 3) << 2;
            float4 v = *(const float4*)&Wih[(size_t)(n0 + n) * ISZ + k0 + k4];
            Bs[k4 + 0][n] = v.x; Bs[k4 + 1][n] = v.y;
            Bs[k4 + 2][n] = v.z; Bs[k4 + 3][n] = v.w;
        }
        __syncthreads();
        #pragma unroll
        for (int k = 0; k < BK; k++) {
            float a[8], b[4];
            #pragma unroll
            for (int i = 0; i < 8; i++) a[i] = As[k][tm * 8 + i];
            #pragma unroll
            for (int j = 0; j < 4; j++) b[j] = Bs[k][tn * 4 + j];
            #pragma unroll
            for (int i = 0; i < 8; i++)
                #pragma unroll
                for (int j = 0; j < 4; j++)
                    acc[i][j] = fmaf(a[i], b[j], acc[i][j]);
        }
        __syncthreads();
    }

    float4 bi = *(const float4*)&bih[n0 + tn * 4];
    float4 bh = *(const float4*)&bhh[n0 + tn * 4];
    float b0 = bi.x + bh.x, b1 = bi.y + bh.y, b2 = bi.z + bh.z, b3 = bi.w + bh.w;
    #pragma unroll
    for (int i = 0; i < 8; i++) {
        float4 o;
        o.x = acc[i][0] + b0; o.y = acc[i][1] + b1;
        o.z = acc[i][2] + b2; o.w = acc[i][3] + b3;
        *(float4*)&g_xp[(size_t)(m0 + tm * 8 + i) * GATES + n0 + tn * 4] = o;
    }
}

// =====================================================================
// Kernel 2: persistent reverse recurrence.
// 128 CTAs x 256 threads, all co-resident (grid barrier via global atomic).
// CTA b owns 8 hidden units j0..j0+7 across all 4 gates = 32 rows of W_hh,
// kept stationary in SMEM (32 x 1024 fp32, padded) for all 512 steps.
// Per step: gates_rec[64 x 32] = h_prev @ W_slab^T, then LSTM update of the
// CTA's 8 hidden columns; h written into out[t], read by everyone next step.
// =====================================================================
#define NCTA 128
#define JPC  8        // hidden units per CTA
#define KC   256      // h K-chunk staged in SMEM
#define WPAD 1028     // 1024 + 4 (16B-aligned, conflict-free float4 LDS)

#define SM_W 0
#define SM_H (32 * WPAD)
#define SM_G (SM_H + 64 * KC)
#define SMEM2_FLOATS (SM_G + 64 * 33)

__device__ __forceinline__ float sigf(float v) { return 1.f / (1.f + __expf(-v)); }

__global__ __launch_bounds__(256) void lstm_recur_kernel(
    const float* __restrict__ h0, const float* __restrict__ c0,
    const float* __restrict__ Whh, float* __restrict__ out, int write_tail)
{
    extern __shared__ float sm[];
    float* w_s = sm + SM_W;   // [32][WPAD]  gate-row gc = q*8+jj -> Whh row q*1024+j0+jj
    float* h_s = sm + SM_H;   // [64][KC]
    float* g_s = sm + SM_G;   // [64][33]

    const int tid  = threadIdx.x;
    const int lane = tid & 31;   // gc: which of the 32 gate rows
    const int warp = tid >> 5;   // 0..7: which group of 8 batch rows
    const int j0   = blockIdx.x * JPC;

    // Preload this CTA's 32 W_hh rows into SMEM (stationary for all steps)
    for (int idx = tid; idx < 32 * HSZ; idx += 256) {
        int gc = idx >> 10;
        int k  = idx & 1023;
        int row = ((gc >> 3) << 10) + j0 + (gc & 7);   // q*1024 + j0 + jj
        w_s[gc * WPAD + k] = Whh[(size_t)row * HSZ + k];
    }
    __syncthreads();

    unsigned target = 0;
    for (int t = T_STEPS - 1; t >= 0; --t) {
        const float* hprev = (t == T_STEPS - 1)
                               ? h0
                               : (out + (size_t)(t + 1) * BATCH * HSZ);
        float acc[8];
        #pragma unroll
        for (int i = 0; i < 8; i++) acc[i] = 0.f;

        for (int kc = 0; kc < HSZ; kc += KC) {
            // Stage h[:, kc:kc+KC] -> SMEM (64*256 floats = 4096 float4, 16/thread)
            #pragma unroll
            for (int i = 0; i < 16; i++) {
                int idx = tid + i * 256;        // 0..4095
                int b   = idx >> 6;             // 0..63
                int c4  = (idx & 63) << 2;      // 0..252
                *(float4*)&h_s[b * KC + c4] =
                    *(const float4*)&hprev[(size_t)b * HSZ + kc + c4];
            }
            __syncthreads();
            // lane gc holds one W row; each thread accumulates 8 batch rows
            #pragma unroll 2
            for (int k = 0; k < KC; k += 4) {
                float4 wv = *(const float4*)&w_s[lane * WPAD + kc + k];
                #pragma unroll
                for (int i = 0; i < 8; i++) {
                    float4 hv = *(const float4*)&h_s[(warp * 8 + i) * KC + k];
                    float s = acc[i];
                    s = fmaf(hv.x, wv.x, s);
                    s = fmaf(hv.y, wv.y, s);
                    s = fmaf(hv.z, wv.z, s);
                    s = fmaf(hv.w, wv.w, s);
                    acc[i] = s;
                }
            }
            __syncthreads();
        }

        // Publish recurrent gate partials to SMEM: g_s[b][gc]
        #pragma unroll
        for (int i = 0; i < 8; i++) g_s[(warp * 8 + i) * 33 + lane] = acc[i];
        __syncthreads();

        // LSTM pointwise update for this CTA's 8 hidden units x 64 batch
        for (int u = tid; u < BATCH * JPC; u += 256) {
            int b  = u >> 3;
            int jj = u & 7;
            int j  = j0 + jj;
            size_t xbase = ((size_t)t * BATCH + b) * GATES;
            float gi = sigf (g_s[b * 33 +      jj] + g_xp[xbase +           j]);
            float gf = sigf (g_s[b * 33 +  8 + jj] + g_xp[xbase +     HSZ + j]);
            float gg = tanhf(g_s[b * 33 + 16 + jj] + g_xp[xbase + 2 * HSZ + j]);
            float go = sigf (g_s[b * 33 + 24 + jj] + g_xp[xbase + 3 * HSZ + j]);
            float cp = (t == T_STEPS - 1) ? c0[b * HSZ + j] : g_c[b * HSZ + j];
            float cn = fmaf(gf, cp, gi * gg);
            float hn = go * tanhf(cn);
            g_c[b * HSZ + j] = cn;
            out[((size_t)t * BATCH + b) * HSZ + j] = hn;
            if (write_tail && t == 0) {
                out[(size_t)T_STEPS * BATCH * HSZ + b * HSZ + j] = hn;            // hT
                out[(size_t)T_STEPS * BATCH * HSZ + BATCH * HSZ + b * HSZ + j] = cn; // cT
            }
        }
        __syncthreads();

        // Grid barrier (monotonic counter: step s passes when count >= (s+1)*NCTA)
        target += NCTA;
        if (tid == 0) {
            __threadfence();
            atomicAdd(&g_count, 1u);
            while (atomicAdd(&g_count, 0u) < target) __nanosleep(128);
            __threadfence();
        }
        __syncthreads();
    }
}

// =====================================================================
// kernel_launch
// =====================================================================
extern "C" void kernel_launch(void* const* d_in, const int* in_sizes, int n_in,
                              void* d_out, int out_size)
{
    const float* x   = (const float*)d_in[0];
    const float* h0  = (const float*)d_in[1];
    const float* c0  = (const float*)d_in[2];
    const float* Wih = (const float*)d_in[3];
    const float* Whh = (const float*)d_in[4];
    const float* bih = (const float*)d_in[5];
    const float* bhh = (const float*)d_in[6];
    float* out = (float*)d_out;

    cudaFuncSetAttribute(lstm_recur_kernel,
                         cudaFuncAttributeMaxDynamicSharedMemorySize,
                         SMEM2_FLOATS * (int)sizeof(float));

    reset_kernel<<<1, 1>>>();

    xp_gemm_kernel<<<dim3(GATES / BN, (T_STEPS * BATCH) / BM), 256>>>(x, Wih, bih, bhh);

    int write_tail = (out_size >= T_STEPS * BATCH * HSZ + 2 * BATCH * HSZ) ? 1 : 0;
    lstm_recur_kernel<<<NCTA, 256, SMEM2_FLOATS * (int)sizeof(float)>>>(
        h0, c0, Whh, out, write_tail);
}

// round 11
// speedup vs baseline: 1.1544x; 1.1544x over previous
#include <cuda_runtime.h>
#include <cuda_bf16.h>
#include <math.h>

// Problem dims
#define T_STEPS 512
#define BATCH   64
#define ISZ     1024
#define HSZ     1024
#define GATES   4096   // 4*HSZ

// -------- scratch (__device__ globals; referenced ONLY from device code) ----
__device__ float g_xp[(size_t)T_STEPS * BATCH * GATES];  // 512 MB: x @ W_ih^T + bias
__device__ float g_c[BATCH * HSZ];                       // cell state
__device__ unsigned g_count;                             // grid barrier counter

__global__ void reset_kernel() { g_count = 0u; }

// =====================================================================
// Kernel 1 (tensor cores): g_xp = x @ Wih^T + (bih + bhh)
//   M=32768, N=4096, K=1024, bf16 split-3 (hh + hl + lh), fp32 accum.
// CTA 128x128, 8 warps (each 64x32), BK=32, static 40KB smem.
// fp32 inputs are loaded directly and split to (hi, lo) bf16 during
// SMEM staging — no separate split kernel, no device-global operands.
// Fragments loaded with plain LDS per the PTX mma.m16n8k16 tables.
// =====================================================================
#define BMX 128
#define BNX 128
#define BKX 32
#define LDT 40   // smem row stride in bf16 (32 data + 8 pad); conflict-free

__device__ __forceinline__ void mma16816(float* c, const unsigned* a, const unsigned* b) {
    asm volatile("mma.sync.aligned.m16n8k16.row.col.f32.bf16.bf16.f32 "
                 "{%0,%1,%2,%3}, {%4,%5,%6,%7}, {%8,%9}, {%0,%1,%2,%3};\n"
                 : "+f"(c[0]), "+f"(c[1]), "+f"(c[2]), "+f"(c[3])
                 : "r"(a[0]), "r"(a[1]), "r"(a[2]), "r"(a[3]), "r"(b[0]), "r"(b[1]));
}

// Split a float4 into packed (hi, lo) bf16 pairs: lo = RN(v - hi)
__device__ __forceinline__ void split4(float4 v, uint2& hi, uint2& lo) {
    __nv_bfloat16 h0 = __float2bfloat16(v.x);
    __nv_bfloat16 h1 = __float2bfloat16(v.y);
    __nv_bfloat16 h2 = __float2bfloat16(v.z);
    __nv_bfloat16 h3 = __float2bfloat16(v.w);
    __nv_bfloat16 l0 = __float2bfloat16(v.x - __bfloat162float(h0));
    __nv_bfloat16 l1 = __float2bfloat16(v.y - __bfloat162float(h1));
    __nv_bfloat16 l2 = __float2bfloat16(v.z - __bfloat162float(h2));
    __nv_bfloat16 l3 = __float2bfloat16(v.w - __bfloat162float(h3));
    __nv_bfloat162 hp0 = __halves2bfloat162(h0, h1);
    __nv_bfloat162 hp1 = __halves2bfloat162(h2, h3);
    __nv_bfloat162 lp0 = __halves2bfloat162(l0, l1);
    __nv_bfloat162 lp1 = __halves2bfloat162(l2, l3);
    hi.x = *(unsigned*)&hp0; hi.y = *(unsigned*)&hp1;
    lo.x = *(unsigned*)&lp0; lo.y = *(unsigned*)&lp1;
}

__global__ __launch_bounds__(256) void xp_mma_kernel(
    const float* __restrict__ x, const float* __restrict__ Wih,
    const float* __restrict__ bih, const float* __restrict__ bhh)
{
    __shared__ __nv_bfloat16 s_ah[BMX][LDT];
    __shared__ __nv_bfloat16 s_al[BMX][LDT];
    __shared__ __nv_bfloat16 s_bh[BNX][LDT];
    __shared__ __nv_bfloat16 s_bl[BNX][LDT];

    const int m0 = blockIdx.y * BMX;
    const int n0 = blockIdx.x * BNX;
    const int tid = threadIdx.x;
    const int lane = tid & 31;
    const int wid = tid >> 5;
    const int wm = wid & 1;    // 2 x 64 rows
    const int wn = wid >> 1;   // 4 x 32 cols
    const int gr = lane >> 2;  // 0..7  (fragment group row)
    const int gc = lane & 3;   // 0..3  (fragment group col)

    float acc[4][4][4];
    #pragma unroll
    for (int i = 0; i < 4; i++)
        #pragma unroll
        for (int j = 0; j < 4; j++)
            #pragma unroll
            for (int r = 0; r < 4; r++) acc[i][j][r] = 0.f;

    for (int kt = 0; kt < ISZ / BKX; kt++) {
        const int k0 = kt * BKX;
        __syncthreads();   // previous iteration's compute done before overwrite
        // Stage tiles: per matrix 128 rows x 32 floats = 1024 float4, 4/thread.
        // Load fp32, split to hi/lo bf16 in registers, store both to SMEM.
        #pragma unroll
        for (int i = 0; i < 4; i++) {
            int c   = tid + i * 256;       // 0..1023
            int row = c >> 3;              // 0..127
            int kc  = (c & 7) << 2;        // 0,4,...,28 (float elems)
            float4 va = *(const float4*)(x   + (size_t)(m0 + row) * ISZ + k0 + kc);
            float4 vb = *(const float4*)(Wih + (size_t)(n0 + row) * ISZ + k0 + kc);
            uint2 h, l;
            split4(va, h, l);
            *(uint2*)&s_ah[row][kc] = h;
            *(uint2*)&s_al[row][kc] = l;
            split4(vb, h, l);
            *(uint2*)&s_bh[row][kc] = h;
            *(uint2*)&s_bl[row][kc] = l;
        }
        __syncthreads();

        #pragma unroll
        for (int ks = 0; ks < 2; ks++) {       // two k16 halves of BK=32
            const int cb = ks * 16 + gc * 2;   // fragment k-col base

            // A fragments per the PTX m16n8k16 table:
            // a0=[r][cb] a1=[r+8][cb] a2=[r][cb+8] a3=[r+8][cb+8]
            unsigned ah[4][4], al[4][4];
            #pragma unroll
            for (int i = 0; i < 4; i++) {
                int r = wm * 64 + i * 16 + gr;
                ah[i][0] = *(const unsigned*)&s_ah[r    ][cb    ];
                ah[i][1] = *(const unsigned*)&s_ah[r + 8][cb    ];
                ah[i][2] = *(const unsigned*)&s_ah[r    ][cb + 8];
                ah[i][3] = *(const unsigned*)&s_ah[r + 8][cb + 8];
                al[i][0] = *(const unsigned*)&s_al[r    ][cb    ];
                al[i][1] = *(const unsigned*)&s_al[r + 8][cb    ];
                al[i][2] = *(const unsigned*)&s_al[r    ][cb + 8];
                al[i][3] = *(const unsigned*)&s_al[r + 8][cb + 8];
            }
            #pragma unroll
            for (int j = 0; j < 4; j++) {
                // B fragment (16Kx8N col): b0=[n][cb], b1=[n][cb+8], n=j*8+gr
                int bn = wn * 32 + j * 8 + gr;
                unsigned bhf[2], blf[2];
                bhf[0] = *(const unsigned*)&s_bh[bn][cb    ];
                bhf[1] = *(const unsigned*)&s_bh[bn][cb + 8];
                blf[0] = *(const unsigned*)&s_bl[bn][cb    ];
                blf[1] = *(const unsigned*)&s_bl[bn][cb + 8];
                #pragma unroll
                for (int i = 0; i < 4; i++) {
                    mma16816(acc[i][j], ah[i], bhf);
                    mma16816(acc[i][j], ah[i], blf);
                    mma16816(acc[i][j], al[i], bhf);
                }
            }
        }
    }

    // ---- epilogue: + (bih+bhh), store fp32 to g_xp ----
    // C fragment: c0/c1 = [gr][gc*2,+1], c2/c3 = [gr+8][gc*2,+1]
    #pragma unroll
    for (int i = 0; i < 4; i++) {
        int r0 = m0 + wm * 64 + i * 16 + gr;
        #pragma unroll
        for (int j = 0; j < 4; j++) {
            int c0 = n0 + wn * 32 + j * 8 + gc * 2;
            float b0 = __ldg(bih + c0) + __ldg(bhh + c0);
            float b1 = __ldg(bih + c0 + 1) + __ldg(bhh + c0 + 1);
            float2 v0 = make_float2(acc[i][j][0] + b0, acc[i][j][1] + b1);
            float2 v1 = make_float2(acc[i][j][2] + b0, acc[i][j][3] + b1);
            *(float2*)&g_xp[(size_t)r0 * GATES + c0] = v0;
            *(float2*)&g_xp[(size_t)(r0 + 8) * GATES + c0] = v1;
        }
    }
}

// =====================================================================
// Kernel 2: persistent reverse recurrence (unchanged, R2-validated).
// =====================================================================
#define NCTA 128
#define JPC  8
#define KC   256
#define WPAD 1028

#define SM_W 0
#define SM_H (32 * WPAD)
#define SM_G (SM_H + 64 * KC)
#define SMEM2_FLOATS (SM_G + 64 * 33)

__device__ __forceinline__ float sigf(float v) { return 1.f / (1.f + __expf(-v)); }

__global__ __launch_bounds__(256) void lstm_recur_kernel(
    const float* __restrict__ h0, const float* __restrict__ c0,
    const float* __restrict__ Whh, float* __restrict__ out, int write_tail)
{
    extern __shared__ float sm[];
    float* w_s = sm + SM_W;
    float* h_s = sm + SM_H;
    float* g_s = sm + SM_G;

    const int tid  = threadIdx.x;
    const int lane = tid & 31;
    const int warp = tid >> 5;
    const int j0   = blockIdx.x * JPC;

    for (int idx = tid; idx < 32 * HSZ; idx += 256) {
        int gc = idx >> 10;
        int k  = idx & 1023;
        int row = ((gc >> 3) << 10) + j0 + (gc & 7);
        w_s[gc * WPAD + k] = Whh[(size_t)row * HSZ + k];
    }
    __syncthreads();

    unsigned target = 0;
    for (int t = T_STEPS - 1; t >= 0; --t) {
        const float* hprev = (t == T_STEPS - 1)
                               ? h0
                               : (out + (size_t)(t + 1) * BATCH * HSZ);
        float acc[8];
        #pragma unroll
        for (int i = 0; i < 8; i++) acc[i] = 0.f;

        for (int kc = 0; kc < HSZ; kc += KC) {
            #pragma unroll
            for (int i = 0; i < 16; i++) {
                int idx = tid + i * 256;
                int b   = idx >> 6;
                int c4  = (idx & 63) << 2;
                *(float4*)&h_s[b * KC + c4] =
                    *(const float4*)&hprev[(size_t)b * HSZ + kc + c4];
            }
            __syncthreads();
            #pragma unroll 2
            for (int k = 0; k < KC; k += 4) {
                float4 wv = *(const float4*)&w_s[lane * WPAD + kc + k];
                #pragma unroll
                for (int i = 0; i < 8; i++) {
                    float4 hv = *(const float4*)&h_s[(warp * 8 + i) * KC + k];
                    float s = acc[i];
                    s = fmaf(hv.x, wv.x, s);
                    s = fmaf(hv.y, wv.y, s);
                    s = fmaf(hv.z, wv.z, s);
                    s = fmaf(hv.w, wv.w, s);
                    acc[i] = s;
                }
            }
            __syncthreads();
        }

        #pragma unroll
        for (int i = 0; i < 8; i++) g_s[(warp * 8 + i) * 33 + lane] = acc[i];
        __syncthreads();

        for (int u = tid; u < BATCH * JPC; u += 256) {
            int b  = u >> 3;
            int jj = u & 7;
            int j  = j0 + jj;
            size_t xbase = ((size_t)t * BATCH + b) * GATES;
            float gi = sigf (g_s[b * 33 +      jj] + g_xp[xbase +           j]);
            float gf = sigf (g_s[b * 33 +  8 + jj] + g_xp[xbase +     HSZ + j]);
            float gg = tanhf(g_s[b * 33 + 16 + jj] + g_xp[xbase + 2 * HSZ + j]);
            float go = sigf (g_s[b * 33 + 24 + jj] + g_xp[xbase + 3 * HSZ + j]);
            float cp = (t == T_STEPS - 1) ? c0[b * HSZ + j] : g_c[b * HSZ + j];
            float cn = fmaf(gf, cp, gi * gg);
            float hn = go * tanhf(cn);
            g_c[b * HSZ + j] = cn;
            out[((size_t)t * BATCH + b) * HSZ + j] = hn;
            if (write_tail && t == 0) {
                out[(size_t)T_STEPS * BATCH * HSZ + b * HSZ + j] = hn;
                out[(size_t)T_STEPS * BATCH * HSZ + BATCH * HSZ + b * HSZ + j] = cn;
            }
        }
        __syncthreads();

        target += NCTA;
        if (tid == 0) {
            __threadfence();
            atomicAdd(&g_count, 1u);
            while (atomicAdd(&g_count, 0u) < target) __nanosleep(128);
            __threadfence();
        }
        __syncthreads();
    }
}

// =====================================================================
// kernel_launch — only harness pointers are passed as kernel arguments;
// all __device__ globals are referenced from device code exclusively.
// =====================================================================
extern "C" void kernel_launch(void* const* d_in, const int* in_sizes, int n_in,
                              void* d_out, int out_size)
{
    const float* x   = (const float*)d_in[0];
    const float* h0  = (const float*)d_in[1];
    const float* c0  = (const float*)d_in[2];
    const float* Wih = (const float*)d_in[3];
    const float* Whh = (const float*)d_in[4];
    const float* bih = (const float*)d_in[5];
    const float* bhh = (const float*)d_in[6];
    float* out = (float*)d_out;

    cudaFuncSetAttribute(lstm_recur_kernel,
                         cudaFuncAttributeMaxDynamicSharedMemorySize,
                         SMEM2_FLOATS * (int)sizeof(float));

    reset_kernel<<<1, 1>>>();

    // Tensor-core xp GEMM with in-kernel fp32 -> bf16 hi/lo split
    xp_mma_kernel<<<dim3(GATES / BNX, (T_STEPS * BATCH) / BMX), 256>>>(
        x, Wih, bih, bhh);

    int write_tail = (out_size >= T_STEPS * BATCH * HSZ + 2 * BATCH * HSZ) ? 1 : 0;
    lstm_recur_kernel<<<NCTA, 256, SMEM2_FLOATS * (int)sizeof(float)>>>(
        h0, c0, Whh, out, write_tail);
}

// round 13
// speedup vs baseline: 2.3121x; 2.0028x over previous
#include <cuda_runtime.h>
#include <cuda_bf16.h>
#include <math.h>

// Problem dims
#define T_STEPS 512
#define BATCH   64
#define ISZ     1024
#define HSZ     1024
#define GATES   4096   // 4*HSZ

// -------- scratch (__device__ globals; referenced ONLY from device code) ----
__device__ float g_xp[(size_t)T_STEPS * BATCH * GATES];  // 512 MB: x @ W_ih^T + bias
__device__ unsigned g_count;                             // grid barrier counter
// h state as pre-split bf16 hi/lo, DOUBLE-BUFFERED by step parity:
// step t reads buffer (t&1), writes buffer 1-(t&1). No read/write aliasing.
__device__ __align__(16) __nv_bfloat16 g_hhi[2][BATCH * HSZ];
__device__ __align__(16) __nv_bfloat16 g_hlo[2][BATCH * HSZ];

__global__ void reset_kernel() { g_count = 0u; }

// =====================================================================
// Common helpers
// =====================================================================
__device__ __forceinline__ void mma16816(float* c, const unsigned* a, const unsigned* b) {
    asm volatile("mma.sync.aligned.m16n8k16.row.col.f32.bf16.bf16.f32 "
                 "{%0,%1,%2,%3}, {%4,%5,%6,%7}, {%8,%9}, {%0,%1,%2,%3};\n"
                 : "+f"(c[0]), "+f"(c[1]), "+f"(c[2]), "+f"(c[3])
                 : "r"(a[0]), "r"(a[1]), "r"(a[2]), "r"(a[3]), "r"(b[0]), "r"(b[1]));
}

// Split a float4 into packed (hi, lo) bf16 pairs: lo = RN(v - hi)
__device__ __forceinline__ void split4(float4 v, uint2& hi, uint2& lo) {
    __nv_bfloat16 h0 = __float2bfloat16(v.x);
    __nv_bfloat16 h1 = __float2bfloat16(v.y);
    __nv_bfloat16 h2 = __float2bfloat16(v.z);
    __nv_bfloat16 h3 = __float2bfloat16(v.w);
    __nv_bfloat16 l0 = __float2bfloat16(v.x - __bfloat162float(h0));
    __nv_bfloat16 l1 = __float2bfloat16(v.y - __bfloat162float(h1));
    __nv_bfloat16 l2 = __float2bfloat16(v.z - __bfloat162float(h2));
    __nv_bfloat16 l3 = __float2bfloat16(v.w - __bfloat162float(h3));
    __nv_bfloat162 hp0 = __halves2bfloat162(h0, h1);
    __nv_bfloat162 hp1 = __halves2bfloat162(h2, h3);
    __nv_bfloat162 lp0 = __halves2bfloat162(l0, l1);
    __nv_bfloat162 lp1 = __halves2bfloat162(l2, l3);
    hi.x = *(unsigned*)&hp0; hi.y = *(unsigned*)&hp1;
    lo.x = *(unsigned*)&lp0; lo.y = *(unsigned*)&lp1;
}

__device__ __forceinline__ float sigf(float v) { return 1.f / (1.f + __expf(-v)); }

// h0 -> bf16 hi/lo split into buffer (T-1)&1 = 1 (read by step t = T-1)
__global__ __launch_bounds__(256) void h0split_kernel(const float* __restrict__ h0) {
    int i = blockIdx.x * blockDim.x + threadIdx.x;   // float4 index
    if (i >= BATCH * HSZ / 4) return;
    float4 v = ((const float4*)h0)[i];
    uint2 h, l;
    split4(v, h, l);
    *(uint2*)&g_hhi[1][i * 4] = h;
    *(uint2*)&g_hlo[1][i * 4] = l;
}

// =====================================================================
// Kernel 1 (tensor cores): g_xp = x @ Wih^T + (bih + bhh)
//   bf16 split-3 (hh + hl + lh), fp32 accum; CTA 128x128, 8 warps, BK=32.
//   Register-prefetch double buffering of the global loads.
// =====================================================================
#define BMX 128
#define BNX 128
#define BKX 32
#define LDT 40   // smem row stride in bf16 (32 data + 8 pad); conflict-free

__global__ __launch_bounds__(256) void xp_mma_kernel(
    const float* __restrict__ x, const float* __restrict__ Wih,
    const float* __restrict__ bih, const float* __restrict__ bhh)
{
    __shared__ __nv_bfloat16 s_ah[BMX][LDT];
    __shared__ __nv_bfloat16 s_al[BMX][LDT];
    __shared__ __nv_bfloat16 s_bh[BNX][LDT];
    __shared__ __nv_bfloat16 s_bl[BNX][LDT];

    const int m0 = blockIdx.y * BMX;
    const int n0 = blockIdx.x * BNX;
    const int tid = threadIdx.x;
    const int lane = tid & 31;
    const int wid = tid >> 5;
    const int wm = wid & 1;    // 2 x 64 rows
    const int wn = wid >> 1;   // 4 x 32 cols
    const int gr = lane >> 2;  // 0..7
    const int gc = lane & 3;   // 0..3

    float acc[4][4][4];
    #pragma unroll
    for (int i = 0; i < 4; i++)
        #pragma unroll
        for (int j = 0; j < 4; j++)
            #pragma unroll
            for (int r = 0; r < 4; r++) acc[i][j][r] = 0.f;

    float4 pa[4], pb[4];
    auto load_regs = [&](int kt) {
        const int k0 = kt * BKX;
        #pragma unroll
        for (int i = 0; i < 4; i++) {
            int c   = tid + i * 256;       // 0..1023
            int row = c >> 3;              // 0..127
            int kc  = (c & 7) << 2;        // 0..28
            pa[i] = *(const float4*)(x   + (size_t)(m0 + row) * ISZ + k0 + kc);
            pb[i] = *(const float4*)(Wih + (size_t)(n0 + row) * ISZ + k0 + kc);
        }
    };

    const int NT = ISZ / BKX;  // 32
    load_regs(0);

    for (int kt = 0; kt < NT; kt++) {
        // split prefetched regs -> smem
        #pragma unroll
        for (int i = 0; i < 4; i++) {
            int c   = tid + i * 256;
            int row = c >> 3;
            int kc  = (c & 7) << 2;
            uint2 h, l;
            split4(pa[i], h, l);
            *(uint2*)&s_ah[row][kc] = h;
            *(uint2*)&s_al[row][kc] = l;
            split4(pb[i], h, l);
            *(uint2*)&s_bh[row][kc] = h;
            *(uint2*)&s_bl[row][kc] = l;
        }
        __syncthreads();
        if (kt + 1 < NT) load_regs(kt + 1);   // LDGs in flight during compute

        #pragma unroll
        for (int ks = 0; ks < 2; ks++) {
            const int cb = ks * 16 + gc * 2;
            unsigned ah[4][4], al[4][4];
            #pragma unroll
            for (int i = 0; i < 4; i++) {
                int r = wm * 64 + i * 16 + gr;
                ah[i][0] = *(const unsigned*)&s_ah[r    ][cb    ];
                ah[i][1] = *(const unsigned*)&s_ah[r + 8][cb    ];
                ah[i][2] = *(const unsigned*)&s_ah[r    ][cb + 8];
                ah[i][3] = *(const unsigned*)&s_ah[r + 8][cb + 8];
                al[i][0] = *(const unsigned*)&s_al[r    ][cb    ];
                al[i][1] = *(const unsigned*)&s_al[r + 8][cb    ];
                al[i][2] = *(const unsigned*)&s_al[r    ][cb + 8];
                al[i][3] = *(const unsigned*)&s_al[r + 8][cb + 8];
            }
            #pragma unroll
            for (int j = 0; j < 4; j++) {
                int bn = wn * 32 + j * 8 + gr;
                unsigned bhf[2], blf[2];
                bhf[0] = *(const unsigned*)&s_bh[bn][cb    ];
                bhf[1] = *(const unsigned*)&s_bh[bn][cb + 8];
                blf[0] = *(const unsigned*)&s_bl[bn][cb    ];
                blf[1] = *(const unsigned*)&s_bl[bn][cb + 8];
                #pragma unroll
                for (int i = 0; i < 4; i++) {
                    mma16816(acc[i][j], ah[i], bhf);
                    mma16816(acc[i][j], ah[i], blf);
                    mma16816(acc[i][j], al[i], bhf);
                }
            }
        }
        __syncthreads();
    }

    // epilogue: + (bih+bhh), store fp32 to g_xp
    #pragma unroll
    for (int i = 0; i < 4; i++) {
        int r0 = m0 + wm * 64 + i * 16 + gr;
        #pragma unroll
        for (int j = 0; j < 4; j++) {
            int c0 = n0 + wn * 32 + j * 8 + gc * 2;
            float b0 = __ldg(bih + c0) + __ldg(bhh + c0);
            float b1 = __ldg(bih + c0 + 1) + __ldg(bhh + c0 + 1);
            float2 v0 = make_float2(acc[i][j][0] + b0, acc[i][j][1] + b1);
            float2 v1 = make_float2(acc[i][j][2] + b0, acc[i][j][3] + b1);
            *(float2*)&g_xp[(size_t)r0 * GATES + c0] = v0;
            *(float2*)&g_xp[(size_t)(r0 + 8) * GATES + c0] = v1;
        }
    }
}

// =====================================================================
// Kernel 2: persistent reverse recurrence on TENSOR CORES.
// 128 CTAs x 256 threads (1/SM), grid barrier. CTA owns 8 hidden units
// (32 W_hh gate-rows, slab row gc = q*8+jj). W slab split to bf16 hi/lo
// ONCE into SMEM (stationary). Per step: h (pre-split bf16 hi/lo,
// parity double-buffered in global) staged in K-chunks of 128;
// 8 warps = wm2 x wn2 x wk2; K-partials reduced via SMEM; pointwise
// update; new h split into the OTHER parity buffer; grid barrier.
// Cell state in registers (CTA-private, no race).
// =====================================================================
#define NCTA 128
#define JPC  8
#define LDW  1032     // W slab row stride (bf16): 1024 + 8
#define KCH  128      // h K-chunk
#define LDH  136      // h chunk row stride (bf16): 128 + 8
#define LDP  33       // partial stride (fp32)

// byte offsets in dynamic smem
#define OFF_WH 0
#define OFF_WL (OFF_WH + 32 * LDW * 2)
#define OFF_HH (OFF_WL + 32 * LDW * 2)
#define OFF_HL (OFF_HH + 64 * LDH * 2)
#define OFF_P  (OFF_HL + 64 * LDH * 2)
#define SMEM_REC_BYTES (OFF_P + 2 * 64 * LDP * 4)   // 183808

__global__ __launch_bounds__(256) void lstm_recur_kernel(
    const float* __restrict__ c0, const float* __restrict__ Whh,
    float* __restrict__ out, int write_tail)
{
    extern __shared__ char smraw[];
    __nv_bfloat16* s_wh = (__nv_bfloat16*)(smraw + OFF_WH);  // [32][LDW]
    __nv_bfloat16* s_wl = (__nv_bfloat16*)(smraw + OFF_WL);
    __nv_bfloat16* s_hh = (__nv_bfloat16*)(smraw + OFF_HH);  // [64][LDH]
    __nv_bfloat16* s_hl = (__nv_bfloat16*)(smraw + OFF_HL);
    float*         s_p  = (float*)(smraw + OFF_P);           // [2][64][LDP]

    const int tid  = threadIdx.x;
    const int lane = tid & 31;
    const int wid  = tid >> 5;
    const int wm   = wid & 1;          // M half (32 batch rows)
    const int wn   = (wid >> 1) & 1;   // N half (16 slab cols)
    const int wk   = wid >> 2;         // K half (512 k each)
    const int gr   = lane >> 2;
    const int gc   = lane & 3;
    const int j0   = blockIdx.x * JPC;

    // ---- Preload + split W slab (stationary all steps) ----
    for (int f4 = tid; f4 < 32 * HSZ / 4; f4 += 256) {
        int e   = f4 * 4;
        int gcr = e >> 10;           // slab row 0..31
        int k   = e & 1023;
        int row = ((gcr >> 3) << 10) + j0 + (gcr & 7);   // q*1024 + j0 + jj
        float4 v = *(const float4*)(Whh + (size_t)row * HSZ + k);
        uint2 h, l;
        split4(v, h, l);
        *(uint2*)&s_wh[gcr * LDW + k] = h;
        *(uint2*)&s_wl[gcr * LDW + k] = l;
    }

    // ---- per-thread cell state: units u = tid, tid+256 -> (b, jj) ----
    float c_reg[2];
    #pragma unroll
    for (int e = 0; e < 2; e++) {
        int u = tid + e * 256;
        int b = u >> 3, jj = u & 7;
        c_reg[e] = c0[b * HSZ + j0 + jj];
    }
    __syncthreads();

    unsigned target = 0;
    for (int t = T_STEPS - 1; t >= 0; --t) {
        const int pr = t & 1;        // read parity
        const int pw = 1 - pr;       // write parity
        const __nv_bfloat16* hhi_r = g_hhi[pr];
        const __nv_bfloat16* hlo_r = g_hlo[pr];

        // prefetch this step's x-path gate values
        float xpg[2][4];
        #pragma unroll
        for (int e = 0; e < 2; e++) {
            int u = tid + e * 256;
            int b = u >> 3, jj = u & 7;
            size_t base = ((size_t)t * BATCH + b) * GATES + j0 + jj;
            xpg[e][0] = g_xp[base];
            xpg[e][1] = g_xp[base +     HSZ];
            xpg[e][2] = g_xp[base + 2 * HSZ];
            xpg[e][3] = g_xp[base + 3 * HSZ];
        }

        float acc[2][2][4];
        #pragma unroll
        for (int i = 0; i < 2; i++)
            #pragma unroll
            for (int j = 0; j < 2; j++)
                #pragma unroll
                for (int r = 0; r < 4; r++) acc[i][j][r] = 0.f;

        for (int kc8 = 0; kc8 < HSZ / KCH; kc8++) {   // 8 chunks
            __syncthreads();   // prior chunk compute done before overwrite
            // stage h chunk: 64 rows x 128 bf16 (hi and lo); uint4 = 8 bf16
            // 64 rows x 16 chunks/row = 1024 = 4 x 256 threads
            #pragma unroll
            for (int i = 0; i < 4; i++) {
                int idx = tid + i * 256;        // 0..1023
                int row = idx >> 4;             // 0..63
                int c16 = (idx & 15) << 3;      // 0..120
                size_t gsrc = (size_t)row * HSZ + kc8 * KCH + c16;
                *(uint4*)&s_hh[row * LDH + c16] = *(const uint4*)&hhi_r[gsrc];
                *(uint4*)&s_hl[row * LDH + c16] = *(const uint4*)&hlo_r[gsrc];
            }
            __syncthreads();

            #pragma unroll
            for (int k16 = 0; k16 < 4; k16++) {   // 4 k16 per warp (wk half)
                const int cbA = wk * 64 + k16 * 16 + gc * 2;
                const int cbB = kc8 * KCH + wk * 64 + k16 * 16 + gc * 2;
                unsigned ah[2][4], al[2][4];
                #pragma unroll
                for (int i = 0; i < 2; i++) {
                    int r = wm * 32 + i * 16 + gr;
                    ah[i][0] = *(const unsigned*)&s_hh[(r    ) * LDH + cbA    ];
                    ah[i][1] = *(const unsigned*)&s_hh[(r + 8) * LDH + cbA    ];
                    ah[i][2] = *(const unsigned*)&s_hh[(r    ) * LDH + cbA + 8];
                    ah[i][3] = *(const unsigned*)&s_hh[(r + 8) * LDH + cbA + 8];
                    al[i][0] = *(const unsigned*)&s_hl[(r    ) * LDH + cbA    ];
                    al[i][1] = *(const unsigned*)&s_hl[(r + 8) * LDH + cbA    ];
                    al[i][2] = *(const unsigned*)&s_hl[(r    ) * LDH + cbA + 8];
                    al[i][3] = *(const unsigned*)&s_hl[(r + 8) * LDH + cbA + 8];
                }
                #pragma unroll
                for (int j = 0; j < 2; j++) {
                    int bn = wn * 16 + j * 8 + gr;
                    unsigned bhf[2], blf[2];
                    bhf[0] = *(const unsigned*)&s_wh[bn * LDW + cbB    ];
                    bhf[1] = *(const unsigned*)&s_wh[bn * LDW + cbB + 8];
                    blf[0] = *(const unsigned*)&s_wl[bn * LDW + cbB    ];
                    blf[1] = *(const unsigned*)&s_wl[bn * LDW + cbB + 8];
                    #pragma unroll
                    for (int i = 0; i < 2; i++) {
                        mma16816(acc[i][j], ah[i], bhf);
                        mma16816(acc[i][j], ah[i], blf);
                        mma16816(acc[i][j], al[i], bhf);
                    }
                }
            }
        }

        // ---- publish K-partials to SMEM ----
        __syncthreads();   // all mma reads of s_hh done before reusing smem region? (s_p separate; sync keeps phases clean)
        #pragma unroll
        for (int i = 0; i < 2; i++) {
            int r0 = wm * 32 + i * 16 + gr;
            #pragma unroll
            for (int j = 0; j < 2; j++) {
                int cc = wn * 16 + j * 8 + gc * 2;
                float* p = s_p + (wk * 64 + r0) * LDP + cc;
                p[0] = acc[i][j][0];
                p[1] = acc[i][j][1];
                p[8 * LDP] = acc[i][j][2];
                p[8 * LDP + 1] = acc[i][j][3];
            }
        }
        __syncthreads();

        // ---- pointwise LSTM update (2 units per thread) ----
        #pragma unroll
        for (int e = 0; e < 2; e++) {
            int u = tid + e * 256;
            int b = u >> 3, jj = u & 7;
            int j = j0 + jj;
            float ri = s_p[b * LDP +      jj] + s_p[(64 + b) * LDP +      jj];
            float rf = s_p[b * LDP +  8 + jj] + s_p[(64 + b) * LDP +  8 + jj];
            float rg = s_p[b * LDP + 16 + jj] + s_p[(64 + b) * LDP + 16 + jj];
            float ro = s_p[b * LDP + 24 + jj] + s_p[(64 + b) * LDP + 24 + jj];
            float gi = sigf (xpg[e][0] + ri);
            float gf = sigf (xpg[e][1] + rf);
            float gg = tanhf(xpg[e][2] + rg);
            float go = sigf (xpg[e][3] + ro);
            float cn = fmaf(gf, c_reg[e], gi * gg);
            c_reg[e] = cn;
            float hn = go * tanhf(cn);
            out[((size_t)t * BATCH + b) * HSZ + j] = hn;
            __nv_bfloat16 hh = __float2bfloat16(hn);
            g_hhi[pw][b * HSZ + j] = hh;
            g_hlo[pw][b * HSZ + j] = __float2bfloat16(hn - __bfloat162float(hh));
            if (write_tail && t == 0) {
                out[(size_t)T_STEPS * BATCH * HSZ + b * HSZ + j] = hn;
                out[(size_t)T_STEPS * BATCH * HSZ + BATCH * HSZ + b * HSZ + j] = cn;
            }
        }
        __syncthreads();

        // ---- grid barrier (monotonic counter) ----
        target += NCTA;
        if (tid == 0) {
            __threadfence();
            atomicAdd(&g_count, 1u);
            while (atomicAdd(&g_count, 0u) < target) __nanosleep(128);
            __threadfence();
        }
        __syncthreads();
    }
}

// =====================================================================
// kernel_launch — only harness pointers cross the host/device boundary.
// =====================================================================
extern "C" void kernel_launch(void* const* d_in, const int* in_sizes, int n_in,
                              void* d_out, int out_size)
{
    const float* x   = (const float*)d_in[0];
    const float* h0  = (const float*)d_in[1];
    const float* c0  = (const float*)d_in[2];
    const float* Wih = (const float*)d_in[3];
    const float* Whh = (const float*)d_in[4];
    const float* bih = (const float*)d_in[5];
    const float* bhh = (const float*)d_in[6];
    float* out = (float*)d_out;

    cudaFuncSetAttribute(lstm_recur_kernel,
                         cudaFuncAttributeMaxDynamicSharedMemorySize,
                         SMEM_REC_BYTES);

    reset_kernel<<<1, 1>>>();
    h0split_kernel<<<(BATCH * HSZ / 4 + 255) / 256, 256>>>(h0);

    xp_mma_kernel<<<dim3(GATES / BNX, (T_STEPS * BATCH) / BMX), 256>>>(
        x, Wih, bih, bhh);

    int write_tail = (out_size >= T_STEPS * BATCH * HSZ + 2 * BATCH * HSZ) ? 1 : 0;
    lstm_recur_kernel<<<NCTA, 256, SMEM_REC_BYTES>>>(
        c0, Whh, out, write_tail);
}

// round 14
// speedup vs baseline: 2.7941x; 1.2085x over previous
#include <cuda_runtime.h>
#include <cuda_bf16.h>
#include <math.h>

// Problem dims
#define T_STEPS 512
#define BATCH   64
#define ISZ     1024
#define HSZ     1024
#define GATES   4096   // 4*HSZ

// -------- scratch (__device__ globals; referenced ONLY from device code) ----
__device__ float g_xp[(size_t)T_STEPS * BATCH * GATES];  // 512 MB: x @ W_ih^T + bias
__device__ unsigned g_count;                             // grid barrier counter
// h state as pre-split bf16 hi/lo, DOUBLE-BUFFERED by step parity:
// step t reads buffer (t&1), writes buffer 1-(t&1). No read/write aliasing.
__device__ __align__(16) __nv_bfloat16 g_hhi[2][BATCH * HSZ];
__device__ __align__(16) __nv_bfloat16 g_hlo[2][BATCH * HSZ];

__global__ void reset_kernel() { g_count = 0u; }

// =====================================================================
// Common helpers
// =====================================================================
__device__ __forceinline__ void mma16816(float* c, const unsigned* a, const unsigned* b) {
    asm volatile("mma.sync.aligned.m16n8k16.row.col.f32.bf16.bf16.f32 "
                 "{%0,%1,%2,%3}, {%4,%5,%6,%7}, {%8,%9}, {%0,%1,%2,%3};\n"
                 : "+f"(c[0]), "+f"(c[1]), "+f"(c[2]), "+f"(c[3])
                 : "r"(a[0]), "r"(a[1]), "r"(a[2]), "r"(a[3]), "r"(b[0]), "r"(b[1]));
}

// Split a float4 into packed (hi, lo) bf16 pairs: lo = RN(v - hi)
__device__ __forceinline__ void split4(float4 v, uint2& hi, uint2& lo) {
    __nv_bfloat16 h0 = __float2bfloat16(v.x);
    __nv_bfloat16 h1 = __float2bfloat16(v.y);
    __nv_bfloat16 h2 = __float2bfloat16(v.z);
    __nv_bfloat16 h3 = __float2bfloat16(v.w);
    __nv_bfloat16 l0 = __float2bfloat16(v.x - __bfloat162float(h0));
    __nv_bfloat16 l1 = __float2bfloat16(v.y - __bfloat162float(h1));
    __nv_bfloat16 l2 = __float2bfloat16(v.z - __bfloat162float(h2));
    __nv_bfloat16 l3 = __float2bfloat16(v.w - __bfloat162float(h3));
    __nv_bfloat162 hp0 = __halves2bfloat162(h0, h1);
    __nv_bfloat162 hp1 = __halves2bfloat162(h2, h3);
    __nv_bfloat162 lp0 = __halves2bfloat162(l0, l1);
    __nv_bfloat162 lp1 = __halves2bfloat162(l2, l3);
    hi.x = *(unsigned*)&hp0; hi.y = *(unsigned*)&hp1;
    lo.x = *(unsigned*)&lp0; lo.y = *(unsigned*)&lp1;
}

__device__ __forceinline__ float sigf(float v) { return 1.f / (1.f + __expf(-v)); }

// h0 -> bf16 hi/lo split into buffer (T-1)&1 = 1 (read by step t = T-1)
__global__ __launch_bounds__(256) void h0split_kernel(const float* __restrict__ h0) {
    int i = blockIdx.x * blockDim.x + threadIdx.x;   // float4 index
    if (i >= BATCH * HSZ / 4) return;
    float4 v = ((const float4*)h0)[i];
    uint2 h, l;
    split4(v, h, l);
    *(uint2*)&g_hhi[1][i * 4] = h;
    *(uint2*)&g_hlo[1][i * 4] = l;
}

// =====================================================================
// Kernel 1 (tensor cores): g_xp = x @ Wih^T + (bih + bhh)
//   bf16 split-3 (hh + hl + lh), fp32 accum.
// CTA 64x128, 8 warps (each 32x32), BK=32, 2 CTAs/SM for overlap.
// Register-prefetch double buffering of the global loads.
// =====================================================================
#define BMX 64
#define BNX 128
#define BKX 32
#define LDT 40   // smem row stride in bf16 (32 data + 8 pad); conflict-free

__global__ __launch_bounds__(256, 2) void xp_mma_kernel(
    const float* __restrict__ x, const float* __restrict__ Wih,
    const float* __restrict__ bih, const float* __restrict__ bhh)
{
    __shared__ __nv_bfloat16 s_ah[BMX][LDT];
    __shared__ __nv_bfloat16 s_al[BMX][LDT];
    __shared__ __nv_bfloat16 s_bh[BNX][LDT];
    __shared__ __nv_bfloat16 s_bl[BNX][LDT];

    const int m0 = blockIdx.y * BMX;
    const int n0 = blockIdx.x * BNX;
    const int tid = threadIdx.x;
    const int lane = tid & 31;
    const int wid = tid >> 5;
    const int wm = wid & 1;    // 2 x 32 rows
    const int wn = wid >> 1;   // 4 x 32 cols
    const int gr = lane >> 2;  // 0..7
    const int gc = lane & 3;   // 0..3

    float acc[2][4][4];
    #pragma unroll
    for (int i = 0; i < 2; i++)
        #pragma unroll
        for (int j = 0; j < 4; j++)
            #pragma unroll
            for (int r = 0; r < 4; r++) acc[i][j][r] = 0.f;

    float4 pa[2], pb[4];
    auto load_regs = [&](int kt) {
        const int k0 = kt * BKX;
        #pragma unroll
        for (int i = 0; i < 2; i++) {            // A: 64 rows = 512 float4
            int c   = tid + i * 256;             // 0..511
            int row = c >> 3;                    // 0..63
            int kc  = (c & 7) << 2;              // 0..28
            pa[i] = *(const float4*)(x + (size_t)(m0 + row) * ISZ + k0 + kc);
        }
        #pragma unroll
        for (int i = 0; i < 4; i++) {            // B: 128 rows = 1024 float4
            int c   = tid + i * 256;             // 0..1023
            int row = c >> 3;                    // 0..127
            int kc  = (c & 7) << 2;
            pb[i] = *(const float4*)(Wih + (size_t)(n0 + row) * ISZ + k0 + kc);
        }
    };

    const int NT = ISZ / BKX;  // 32
    load_regs(0);

    for (int kt = 0; kt < NT; kt++) {
        // split prefetched regs -> smem
        #pragma unroll
        for (int i = 0; i < 2; i++) {
            int c   = tid + i * 256;
            int row = c >> 3;
            int kc  = (c & 7) << 2;
            uint2 h, l;
            split4(pa[i], h, l);
            *(uint2*)&s_ah[row][kc] = h;
            *(uint2*)&s_al[row][kc] = l;
        }
        #pragma unroll
        for (int i = 0; i < 4; i++) {
            int c   = tid + i * 256;
            int row = c >> 3;
            int kc  = (c & 7) << 2;
            uint2 h, l;
            split4(pb[i], h, l);
            *(uint2*)&s_bh[row][kc] = h;
            *(uint2*)&s_bl[row][kc] = l;
        }
        __syncthreads();
        if (kt + 1 < NT) load_regs(kt + 1);   // LDGs in flight during compute

        #pragma unroll
        for (int ks = 0; ks < 2; ks++) {
            const int cb = ks * 16 + gc * 2;
            unsigned ah[2][4], al[2][4];
            #pragma unroll
            for (int i = 0; i < 2; i++) {
                int r = wm * 32 + i * 16 + gr;
                ah[i][0] = *(const unsigned*)&s_ah[r    ][cb    ];
                ah[i][1] = *(const unsigned*)&s_ah[r + 8][cb    ];
                ah[i][2] = *(const unsigned*)&s_ah[r    ][cb + 8];
                ah[i][3] = *(const unsigned*)&s_ah[r + 8][cb + 8];
                al[i][0] = *(const unsigned*)&s_al[r    ][cb    ];
                al[i][1] = *(const unsigned*)&s_al[r + 8][cb    ];
                al[i][2] = *(const unsigned*)&s_al[r    ][cb + 8];
                al[i][3] = *(const unsigned*)&s_al[r + 8][cb + 8];
            }
            #pragma unroll
            for (int j = 0; j < 4; j++) {
                int bn = wn * 32 + j * 8 + gr;
                unsigned bhf[2], blf[2];
                bhf[0] = *(const unsigned*)&s_bh[bn][cb    ];
                bhf[1] = *(const unsigned*)&s_bh[bn][cb + 8];
                blf[0] = *(const unsigned*)&s_bl[bn][cb    ];
                blf[1] = *(const unsigned*)&s_bl[bn][cb + 8];
                #pragma unroll
                for (int i = 0; i < 2; i++) {
                    mma16816(acc[i][j], ah[i], bhf);
                    mma16816(acc[i][j], ah[i], blf);
                    mma16816(acc[i][j], al[i], bhf);
                }
            }
        }
        __syncthreads();
    }

    // epilogue: + (bih+bhh), store fp32 to g_xp
    #pragma unroll
    for (int i = 0; i < 2; i++) {
        int r0 = m0 + wm * 32 + i * 16 + gr;
        #pragma unroll
        for (int j = 0; j < 4; j++) {
            int c0 = n0 + wn * 32 + j * 8 + gc * 2;
            float b0 = __ldg(bih + c0) + __ldg(bhh + c0);
            float b1 = __ldg(bih + c0 + 1) + __ldg(bhh + c0 + 1);
            float2 v0 = make_float2(acc[i][j][0] + b0, acc[i][j][1] + b1);
            float2 v1 = make_float2(acc[i][j][2] + b0, acc[i][j][3] + b1);
            *(float2*)&g_xp[(size_t)r0 * GATES + c0] = v0;
            *(float2*)&g_xp[(size_t)(r0 + 8) * GATES + c0] = v1;
        }
    }
}

// =====================================================================
// Kernel 2: persistent reverse recurrence on TENSOR CORES.
// As R13 (validated), plus register-prefetch of the next h chunk so the
// L2 loads overlap the mma compute of the current chunk.
// =====================================================================
#define NCTA 128
#define JPC  8
#define LDW  1032     // W slab row stride (bf16): 1024 + 8
#define KCH  128      // h K-chunk
#define LDH  136      // h chunk row stride (bf16): 128 + 8
#define LDP  33       // partial stride (fp32)

// byte offsets in dynamic smem
#define OFF_WH 0
#define OFF_WL (OFF_WH + 32 * LDW * 2)
#define OFF_HH (OFF_WL + 32 * LDW * 2)
#define OFF_HL (OFF_HH + 64 * LDH * 2)
#define OFF_P  (OFF_HL + 64 * LDH * 2)
#define SMEM_REC_BYTES (OFF_P + 2 * 64 * LDP * 4)   // 183808

__global__ __launch_bounds__(256) void lstm_recur_kernel(
    const float* __restrict__ c0, const float* __restrict__ Whh,
    float* __restrict__ out, int write_tail)
{
    extern __shared__ char smraw[];
    __nv_bfloat16* s_wh = (__nv_bfloat16*)(smraw + OFF_WH);  // [32][LDW]
    __nv_bfloat16* s_wl = (__nv_bfloat16*)(smraw + OFF_WL);
    __nv_bfloat16* s_hh = (__nv_bfloat16*)(smraw + OFF_HH);  // [64][LDH]
    __nv_bfloat16* s_hl = (__nv_bfloat16*)(smraw + OFF_HL);
    float*         s_p  = (float*)(smraw + OFF_P);           // [2][64][LDP]

    const int tid  = threadIdx.x;
    const int lane = tid & 31;
    const int wid  = tid >> 5;
    const int wm   = wid & 1;          // M half (32 batch rows)
    const int wn   = (wid >> 1) & 1;   // N half (16 slab cols)
    const int wk   = wid >> 2;         // K half (512 k each)
    const int gr   = lane >> 2;
    const int gc   = lane & 3;
    const int j0   = blockIdx.x * JPC;

    // ---- Preload + split W slab (stationary all steps) ----
    for (int f4 = tid; f4 < 32 * HSZ / 4; f4 += 256) {
        int e   = f4 * 4;
        int gcr = e >> 10;           // slab row 0..31
        int k   = e & 1023;
        int row = ((gcr >> 3) << 10) + j0 + (gcr & 7);   // q*1024 + j0 + jj
        float4 v = *(const float4*)(Whh + (size_t)row * HSZ + k);
        uint2 h, l;
        split4(v, h, l);
        *(uint2*)&s_wh[gcr * LDW + k] = h;
        *(uint2*)&s_wl[gcr * LDW + k] = l;
    }

    // ---- per-thread cell state: units u = tid, tid+256 -> (b, jj) ----
    float c_reg[2];
    #pragma unroll
    for (int e = 0; e < 2; e++) {
        int u = tid + e * 256;
        int b = u >> 3, jj = u & 7;
        c_reg[e] = c0[b * HSZ + j0 + jj];
    }
    __syncthreads();

    unsigned target = 0;
    for (int t = T_STEPS - 1; t >= 0; --t) {
        const int pr = t & 1;        // read parity
        const int pw = 1 - pr;       // write parity
        const __nv_bfloat16* hhi_r = g_hhi[pr];
        const __nv_bfloat16* hlo_r = g_hlo[pr];

        // prefetch this step's x-path gate values
        float xpg[2][4];
        #pragma unroll
        for (int e = 0; e < 2; e++) {
            int u = tid + e * 256;
            int b = u >> 3, jj = u & 7;
            size_t base = ((size_t)t * BATCH + b) * GATES + j0 + jj;
            xpg[e][0] = g_xp[base];
            xpg[e][1] = g_xp[base +     HSZ];
            xpg[e][2] = g_xp[base + 2 * HSZ];
            xpg[e][3] = g_xp[base + 3 * HSZ];
        }

        float acc[2][2][4];
        #pragma unroll
        for (int i = 0; i < 2; i++)
            #pragma unroll
            for (int j = 0; j < 2; j++)
                #pragma unroll
                for (int r = 0; r < 4; r++) acc[i][j][r] = 0.f;

        // register prefetch of h chunks (hi/lo): 4 uint4 each per thread
        uint4 ph[4], pl[4];
        auto ldchunk = [&](int kc8) {
            #pragma unroll
            for (int i = 0; i < 4; i++) {
                int idx = tid + i * 256;        // 0..1023
                int row = idx >> 4;             // 0..63
                int c16 = (idx & 15) << 3;      // 0..120
                size_t gsrc = (size_t)row * HSZ + kc8 * KCH + c16;
                ph[i] = *(const uint4*)&hhi_r[gsrc];
                pl[i] = *(const uint4*)&hlo_r[gsrc];
            }
        };
        ldchunk(0);

        for (int kc8 = 0; kc8 < HSZ / KCH; kc8++) {   // 8 chunks
            __syncthreads();   // prior chunk mma reads done before overwrite
            #pragma unroll
            for (int i = 0; i < 4; i++) {
                int idx = tid + i * 256;
                int row = idx >> 4;
                int c16 = (idx & 15) << 3;
                *(uint4*)&s_hh[row * LDH + c16] = ph[i];
                *(uint4*)&s_hl[row * LDH + c16] = pl[i];
            }
            __syncthreads();
            if (kc8 + 1 < HSZ / KCH) ldchunk(kc8 + 1);  // LDGs overlap mma

            #pragma unroll
            for (int k16 = 0; k16 < 4; k16++) {   // 4 k16 per warp (wk half)
                const int cbA = wk * 64 + k16 * 16 + gc * 2;
                const int cbB = kc8 * KCH + wk * 64 + k16 * 16 + gc * 2;
                unsigned ah[2][4], al[2][4];
                #pragma unroll
                for (int i = 0; i < 2; i++) {
                    int r = wm * 32 + i * 16 + gr;
                    ah[i][0] = *(const unsigned*)&s_hh[(r    ) * LDH + cbA    ];
                    ah[i][1] = *(const unsigned*)&s_hh[(r + 8) * LDH + cbA    ];
                    ah[i][2] = *(const unsigned*)&s_hh[(r    ) * LDH + cbA + 8];
                    ah[i][3] = *(const unsigned*)&s_hh[(r + 8) * LDH + cbA + 8];
                    al[i][0] = *(const unsigned*)&s_hl[(r    ) * LDH + cbA    ];
                    al[i][1] = *(const unsigned*)&s_hl[(r + 8) * LDH + cbA    ];
                    al[i][2] = *(const unsigned*)&s_hl[(r    ) * LDH + cbA + 8];
                    al[i][3] = *(const unsigned*)&s_hl[(r + 8) * LDH + cbA + 8];
                }
                #pragma unroll
                for (int j = 0; j < 2; j++) {
                    int bn = wn * 16 + j * 8 + gr;
                    unsigned bhf[2], blf[2];
                    bhf[0] = *(const unsigned*)&s_wh[bn * LDW + cbB    ];
                    bhf[1] = *(const unsigned*)&s_wh[bn * LDW + cbB + 8];
                    blf[0] = *(const unsigned*)&s_wl[bn * LDW + cbB    ];
                    blf[1] = *(const unsigned*)&s_wl[bn * LDW + cbB + 8];
                    #pragma unroll
                    for (int i = 0; i < 2; i++) {
                        mma16816(acc[i][j], ah[i], bhf);
                        mma16816(acc[i][j], ah[i], blf);
                        mma16816(acc[i][j], al[i], bhf);
                    }
                }
            }
        }

        // ---- publish K-partials to SMEM ----
        __syncthreads();
        #pragma unroll
        for (int i = 0; i < 2; i++) {
            int r0 = wm * 32 + i * 16 + gr;
            #pragma unroll
            for (int j = 0; j < 2; j++) {
                int cc = wn * 16 + j * 8 + gc * 2;
                float* p = s_p + (wk * 64 + r0) * LDP + cc;
                p[0] = acc[i][j][0];
                p[1] = acc[i][j][1];
                p[8 * LDP] = acc[i][j][2];
                p[8 * LDP + 1] = acc[i][j][3];
            }
        }
        __syncthreads();

        // ---- pointwise LSTM update (2 units per thread) ----
        #pragma unroll
        for (int e = 0; e < 2; e++) {
            int u = tid + e * 256;
            int b = u >> 3, jj = u & 7;
            int j = j0 + jj;
            float ri = s_p[b * LDP +      jj] + s_p[(64 + b) * LDP +      jj];
            float rf = s_p[b * LDP +  8 + jj] + s_p[(64 + b) * LDP +  8 + jj];
            float rg = s_p[b * LDP + 16 + jj] + s_p[(64 + b) * LDP + 16 + jj];
            float ro = s_p[b * LDP + 24 + jj] + s_p[(64 + b) * LDP + 24 + jj];
            float gi = sigf (xpg[e][0] + ri);
            float gf = sigf (xpg[e][1] + rf);
            float gg = tanhf(xpg[e][2] + rg);
            float go = sigf (xpg[e][3] + ro);
            float cn = fmaf(gf, c_reg[e], gi * gg);
            c_reg[e] = cn;
            float hn = go * tanhf(cn);
            out[((size_t)t * BATCH + b) * HSZ + j] = hn;
            __nv_bfloat16 hh = __float2bfloat16(hn);
            g_hhi[pw][b * HSZ + j] = hh;
            g_hlo[pw][b * HSZ + j] = __float2bfloat16(hn - __bfloat162float(hh));
            if (write_tail && t == 0) {
                out[(size_t)T_STEPS * BATCH * HSZ + b * HSZ + j] = hn;
                out[(size_t)T_STEPS * BATCH * HSZ + BATCH * HSZ + b * HSZ + j] = cn;
            }
        }
        __syncthreads();

        // ---- grid barrier (monotonic counter) ----
        target += NCTA;
        if (tid == 0) {
            __threadfence();
            atomicAdd(&g_count, 1u);
            while (atomicAdd(&g_count, 0u) < target) __nanosleep(32);
            __threadfence();
        }
        __syncthreads();
    }
}

// =====================================================================
// kernel_launch — only harness pointers cross the host/device boundary.
// =====================================================================
extern "C" void kernel_launch(void* const* d_in, const int* in_sizes, int n_in,
                              void* d_out, int out_size)
{
    const float* x   = (const float*)d_in[0];
    const float* h0  = (const float*)d_in[1];
    const float* c0  = (const float*)d_in[2];
    const float* Wih = (const float*)d_in[3];
    const float* Whh = (const float*)d_in[4];
    const float* bih = (const float*)d_in[5];
    const float* bhh = (const float*)d_in[6];
    float* out = (float*)d_out;

    cudaFuncSetAttribute(lstm_recur_kernel,
                         cudaFuncAttributeMaxDynamicSharedMemorySize,
                         SMEM_REC_BYTES);

    reset_kernel<<<1, 1>>>();
    h0split_kernel<<<(BATCH * HSZ / 4 + 255) / 256, 256>>>(h0);

    xp_mma_kernel<<<dim3(GATES / BNX, (T_STEPS * BATCH) / BMX), 256>>>(
        x, Wih, bih, bhh);

    int write_tail = (out_size >= T_STEPS * BATCH * HSZ + 2 * BATCH * HSZ) ? 1 : 0;
    lstm_recur_kernel<<<NCTA, 256, SMEM_REC_BYTES>>>(
        c0, Whh, out, write_tail);
}